// round 5
// baseline (speedup 1.0000x reference)
#include <cuda_runtime.h>

#define BB 4
#define HH 256
#define WW 256
#define NN 256
#define GRID 256
#define TPB 256

// Scratch (static __device__ arrays: allocation-free).
__device__ float2 g_gimg2[BB * HH * WW];  // interleaved (ygrad, xgrad) of pred
__device__ float  g_gw[BB * HH * WW];     // channel-summed grad of |pred|
__device__ int    g_dmap[BB * HH * WW];   // float bits, init 15.0f
__device__ float  g_py[BB * NN], g_px[BB * NN], g_wd[BB * NN];
__device__ double g_part[GRID];
__device__ unsigned g_bars[4];            // grid-barrier arrive counters
__device__ unsigned g_exit;               // exit counter for state reset

// ---------------------------------------------------------------------------
// Grid barrier: counting arrive + spin. All GRID blocks are co-resident
// (256 blocks <= 148 SMs x 2; 20KB smem, <=128 regs). Trailing __threadfence
// is gpu-scope -> CCTL.IVALL, so post-barrier loads can't hit stale L1.
// ---------------------------------------------------------------------------
__device__ __forceinline__ void gbar(int idx) {
    __syncthreads();
    __threadfence();
    if (threadIdx.x == 0) {
        atomicAdd(&g_bars[idx], 1u);
        while (*(volatile unsigned*)&g_bars[idx] < GRID) __nanosleep(128);
    }
    __syncthreads();
    __threadfence();
}

struct SmemPool {
    union {
        struct { float in[44][48]; float hg[44][32]; float hd[44][32]; } conv;
        struct { float y[2][NN]; float x[2][NN]; float w[2][NN]; } snake;
        struct { float wsum[8]; double sd[GRID]; } red;
    };
};

__device__ __forceinline__ void bilin_setup(float y, float x, int& off, float& ty, float& tx) {
    y = fminf(fmaxf(y, 0.0f), 254.999f);  // H - 1.001
    x = fminf(fmaxf(x, 0.0f), 254.999f);
    float fy = floorf(y), fx = floorf(x);
    off = (int)fy * WW + (int)fx;
    ty = y - fy;
    tx = x - fx;
}

__global__ void __launch_bounds__(TPB, 2)
fused_kernel(const float* __restrict__ pred, const float* __restrict__ node_pos,
             const float* __restrict__ widths, float* __restrict__ out) {
    __shared__ SmemPool sp;
    const int t = threadIdx.x;

    // =====================================================================
    // Phase A: separable 13x13 edge conv, coefficients as FP32 immediates.
    // 512 tile-jobs (b x {signed,abs} x 64 tiles); each block does 2.
    // =====================================================================
    {
        // g /= g.sum(); dg = -x/stdev^2 * g, stdev=2, taps at x=-6..6.
        constexpr float KG[13] = {
            0.00221820f, 0.00877313f, 0.02702315f, 0.06482518f, 0.12110938f,
            0.17621311f, 0.19967563f, 0.17621311f, 0.12110938f, 0.06482518f,
            0.02702315f, 0.00877313f, 0.00221820f};
        constexpr float KD[13] = {
            0.00332730f, 0.01096641f, 0.02702315f, 0.04861888f, 0.06055469f,
            0.04405328f, 0.00000000f, -0.04405328f, -0.06055469f, -0.04861888f,
            -0.02702315f, -0.01096641f, -0.00332730f};

        for (int rep = 0; rep < 2; rep++) {
            __syncthreads();  // protect smem reuse across reps
            const int job = blockIdx.x + rep * GRID;  // 0..511
            const int mode = (job >> 6) & 1;
            const int b = job >> 7;
            const int tile = job & 63;
            const int ty0 = (tile >> 3) * 32, tx0 = (tile & 7) * 32;
            const float* xb = pred + b * HH * WW;

            // Load 44x44 input tile with 6-px halo, zero padding; abs if mode1.
            for (int idx = t; idx < 44 * 44; idx += TPB) {
                int iy = idx / 44, ix = idx % 44;
                int gy = ty0 + iy - 6, gx = tx0 + ix - 6;
                float v = 0.0f;
                if ((unsigned)gy < HH && (unsigned)gx < WW) v = xb[gy * WW + gx];
                sp.conv.in[iy][ix] = mode ? fabsf(v) : v;
            }
            __syncthreads();

            // Horizontal pass.
            for (int idx = t; idx < 44 * 32; idx += TPB) {
                int iy = idx / 32, ix = idx % 32;
                float hg = 0.f, hd = 0.f;
#pragma unroll
                for (int l = 0; l < 13; l++) {
                    float v = sp.conv.in[iy][ix + l];
                    hg = fmaf(v, KG[l], hg);
                    hd = fmaf(v, KD[l], hd);
                }
                sp.conv.hg[iy][ix] = hg;
                sp.conv.hd[iy][ix] = hd;
            }
            __syncthreads();

            // Vertical pass.
            for (int idx = t; idx < 32 * 32; idx += TPB) {
                int iy = idx / 32, ix = idx % 32;
                float c0 = 0.f, c1 = 0.f;
#pragma unroll
                for (int k = 0; k < 13; k++) {
                    c0 = fmaf(sp.conv.hg[iy + k][ix], KD[k], c0);
                    c1 = fmaf(sp.conv.hd[iy + k][ix], KG[k], c1);
                }
                int o = (b * HH + ty0 + iy) * WW + tx0 + ix;
                if (mode == 0) {
                    g_gimg2[o] = make_float2(10.0f * c0, 10.0f * c1);  // EXTGRADFAC
                } else {
                    g_gw[o] = 10.0f * (c0 + c1);
                    g_dmap[o] = 0x41700000;  // 15.0f (DMAX)
                }
            }
        }
    }
    gbar(0);

    // =====================================================================
    // Phase B: snake optimization. Blocks 0..3 (one per batch); one thread
    // per node; ping-pong smem state, single bar per step. Other blocks wait.
    // =====================================================================
    if (blockIdx.x < BB) {
        const int b = blockIdx.x;
        const int i = t;
        const int im1 = max(i - 1, 0), ip1 = min(i + 1, NN - 1);
        const int a0 = max(i - 2, 0);
        const int a1 = (i >= 1) ? i : 1;
        const int b0 = (i <= NN - 2) ? i : NN - 2;
        const int b1 = min(i + 2, NN - 1);

        sp.snake.y[0][i] = node_pos[(b * NN + i) * 2 + 0];
        sp.snake.x[0][i] = node_pos[(b * NN + i) * 2 + 1];
        sp.snake.w[0][i] = widths[b * NN + i];
        const float2* gi = g_gimg2 + b * HH * WW;
        const float* gw = g_gw + b * HH * WW;
        __syncthreads();

        int cur = 0;
#pragma unroll 1
        for (int s = 0; s < 50; s++) {
            const float* py = sp.snake.y[cur];
            const float* px = sp.snake.x[cur];
            const float* pw = sp.snake.w[cur];
            float pyi = py[i], pxi = px[i];

            int off; float ty, tx;
            bilin_setup(pyi, pxi, off, ty, tx);
            float2 v00 = gi[off], v01 = gi[off + 1], v10 = gi[off + WW], v11 = gi[off + WW + 1];
            float w00 = (1.f - ty) * (1.f - tx), w01 = (1.f - ty) * tx;
            float w10 = ty * (1.f - tx), w11 = ty * tx;
            float fY = v00.x * w00 + v01.x * w01 + v10.x * w10 + v11.x * w11;
            float fX = v00.y * w00 + v01.y * w01 + v10.y * w10 + v11.y * w11;

            float d2ym = py[a0] - 2.f * py[im1] + py[a1];
            float d2yc = py[im1] - 2.f * pyi + py[ip1];
            float d2yp = py[b0] - 2.f * py[ip1] + py[b1];
            float d4y = d2ym - 2.f * d2yc + d2yp;
            float d2xm = px[a0] - 2.f * px[im1] + px[a1];
            float d2xc = px[im1] - 2.f * pxi + px[ip1];
            float d2xp = px[b0] - 2.f * px[ip1] + px[b1];
            float d4x = d2xm - 2.f * d2xc + d2xp;

            float npy = pyi + 0.1f * (0.01f * d2yc - 0.005f * d4y + fY);
            float npx = pxi + 0.1f * (0.01f * d2xc - 0.005f * d4x + fX);
            npy = fminf(fmaxf(npy, 0.0f), 255.0f);
            npx = fminf(fmaxf(npx, 0.0f), 255.0f);

            float wi = pw[i];
            float d2w = pw[im1] - 2.f * wi + pw[ip1];
            int off2; float ty2, tx2;
            bilin_setup(npy, npx, off2, ty2, tx2);
            float u00 = gw[off2], u01 = gw[off2 + 1], u10 = gw[off2 + WW], u11 = gw[off2 + WW + 1];
            float fw = u00 * (1.f - ty2) * (1.f - tx2) + u01 * (1.f - ty2) * tx2 +
                       u10 * ty2 * (1.f - tx2) + u11 * ty2 * tx2;
            float nwi = wi + 0.1f * (0.01f * d2w + fw);
            nwi = fminf(fmaxf(nwi, 0.0f), 15.0f);

            int nxt = cur ^ 1;
            sp.snake.y[nxt][i] = npy;
            sp.snake.x[nxt][i] = npx;
            sp.snake.w[nxt][i] = nwi;
            __syncthreads();
            cur = nxt;
        }
        g_py[b * NN + i] = sp.snake.y[cur][i];
        g_px[b * NN + i] = sp.snake.x[cur][i];
        g_wd[b * NN + i] = sp.snake.w[cur][i];
    }
    gbar(1);

    // =====================================================================
    // Phase C: scatter render. 1024 (b,node) jobs; each block does 4.
    // Rasterize influence disk (radius w+DMAX <= 30), atomicMin float bits.
    // =====================================================================
    for (int rep = 0; rep < 4; rep++) {
        const int job = blockIdx.x + rep * GRID;  // 0..1023
        const int b = job >> 8;
        const int j = job & 255;
        const float py = g_py[b * NN + j];
        const float px = g_px[b * NN + j];
        const float w = g_wd[b * NN + j];
        const float R = w + 15.0f;
        const float R2 = R * R;

        int y0 = max((int)ceilf(py - R), 0);
        int y1 = min((int)floorf(py + R), HH - 1);
        int x0 = max((int)ceilf(px - R), 0);
        int x1 = min((int)floorf(px + R), WW - 1);

        const int c = t & 63;   // column within box (width <= 61)
        const int rb = t >> 6;  // 4 row phases
        const int xg = x0 + c;
        if (xg <= x1) {
            const float dx = (float)xg - px;
            const float dx2 = dx * dx;
            int* dmap = g_dmap + b * HH * WW;
            for (int y = y0 + rb; y <= y1; y += 4) {
                float dy = (float)y - py;
                float r2 = fmaf(dy, dy, dx2);
                if (r2 < R2) {
                    r2 = fmaxf(r2, 1e-18f);
                    float d = fmaf(r2, rsqrtf(r2), -w);  // sqrt(r2) - w
                    d = fmaxf(d, 0.0f);
                    atomicMin(&dmap[y * WW + xg], __float_as_int(d));
                }
            }
        }
    }
    gbar(2);

    // =====================================================================
    // Phase D: MSE partials (1024 px per block), then block-0 final reduce.
    // =====================================================================
    {
        const int base = (blockIdx.x * TPB + t) * 4;
        float4 p = *(const float4*)(pred + base);
        int4 dm = *(const int4*)(g_dmap + base);
        float e0 = p.x - __int_as_float(dm.x);
        float e1 = p.y - __int_as_float(dm.y);
        float e2 = p.z - __int_as_float(dm.z);
        float e3 = p.w - __int_as_float(dm.w);
        float acc = fmaf(e0, e0, fmaf(e1, e1, fmaf(e2, e2, e3 * e3)));
#pragma unroll
        for (int o = 16; o > 0; o >>= 1) acc += __shfl_xor_sync(0xffffffffu, acc, o);
        if ((t & 31) == 0) sp.red.wsum[t >> 5] = acc;
        __syncthreads();
        if (t == 0) {
            float s = 0.0f;
#pragma unroll
            for (int k = 0; k < 8; k++) s += sp.red.wsum[k];
            g_part[blockIdx.x] = (double)s;
        }
    }
    gbar(3);

    if (blockIdx.x == 0) {
        sp.red.sd[t] = g_part[t];
        __syncthreads();
        for (int o = 128; o > 0; o >>= 1) {
            if (t < o) sp.red.sd[t] += sp.red.sd[t + o];
            __syncthreads();
        }
        if (t == 0) out[0] = (float)(sp.red.sd[0] / (double)(BB * HH * WW));
    }

    // Exit accounting: the LAST block to leave resets barrier state so the
    // next graph replay starts clean. Nobody reads g_bars after their final
    // barrier, so this cannot race with a spinning reader.
    __syncthreads();
    if (t == 0) {
        unsigned v = atomicAdd(&g_exit, 1u);
        if (v == GRID - 1) {
            g_bars[0] = 0; g_bars[1] = 0; g_bars[2] = 0; g_bars[3] = 0;
            __threadfence();
            g_exit = 0;
        }
    }
}

extern "C" void kernel_launch(void* const* d_in, const int* in_sizes, int n_in,
                              void* d_out, int out_size) {
    const float* pred = (const float*)d_in[0];      // (4,1,256,256)
    const float* node_pos = (const float*)d_in[1];  // (4,256,2)
    const float* widths = (const float*)d_in[2];    // (4,256)
    (void)in_sizes; (void)n_in; (void)out_size;

    fused_kernel<<<GRID, TPB>>>(pred, node_pos, widths, (float*)d_out);
}